// round 14
// baseline (speedup 1.0000x reference)
#include <cuda_runtime.h>
#include <cuda_fp16.h>
#include <cstdint>

#define N_NODES 50000
#define N_EDGES 800000
#define C 128
#define BUCKET 128
#define BN_EPS 1e-5f

// ================= PTX helpers (sm_100-safe: mma.sync / ldmatrix / cp.async) =================
__device__ __forceinline__ uint32_t smem_u32(const void* p) {
    uint32_t a;
    asm("{ .reg .u64 t; cvta.to.shared.u64 t, %1; cvt.u32.u64 %0, t; }" : "=r"(a) : "l"(p));
    return a;
}
__device__ __forceinline__ void cpa16(uint32_t dst, const void* src, uint32_t sz) {
    asm volatile("cp.async.cg.shared.global [%0], [%1], 16, %2;" :: "r"(dst), "l"(src), "r"(sz));
}
#define CP_COMMIT() asm volatile("cp.async.commit_group;" ::: "memory")
__device__ __forceinline__ void ldsm_x4(uint32_t* r, uint32_t a) {
    asm volatile("ldmatrix.sync.aligned.m8n8.x4.shared.b16 {%0,%1,%2,%3}, [%4];"
                 : "=r"(r[0]), "=r"(r[1]), "=r"(r[2]), "=r"(r[3]) : "r"(a));
}
__device__ __forceinline__ void ldsm_x2(uint32_t* r, uint32_t a) {
    asm volatile("ldmatrix.sync.aligned.m8n8.x2.shared.b16 {%0,%1}, [%2];"
                 : "=r"(r[0]), "=r"(r[1]) : "r"(a));
}
__device__ __forceinline__ void mma16816(float* d, const uint32_t* a, const uint32_t* b) {
    asm volatile(
        "mma.sync.aligned.m16n8k16.row.col.f32.f16.f16.f32 "
        "{%0,%1,%2,%3},{%4,%5,%6,%7},{%8,%9},{%0,%1,%2,%3};"
        : "+f"(d[0]), "+f"(d[1]), "+f"(d[2]), "+f"(d[3])
        : "r"(a[0]), "r"(a[1]), "r"(a[2]), "r"(a[3]), "r"(b[0]), "r"(b[1]));
}

// ================= scratch =================
__device__ int   g_cnt[N_NODES];                       // per-node degree counter
__device__ int2  g_edge[(size_t)N_NODES * BUCKET];     // bucketed edges (src, half2{w,w} bits)
__device__ __half g_hf[N_NODES * C];     // fp16 pre-BN activations (layers 0/1)
__device__ __half g_xf[N_NODES * C];     // fp16 features (gather + GEMM X operand + residual)
__device__ __half g_aggf[N_NODES * C];   // fp16 aggregation result (GEMM A operand)
// B slices per layer: id = path*2 + khalf -> 4 slices of [NN][64] fp16 (W-hi only)
__device__ __half g_bt0[4 * 128 * 64];
__device__ __half g_bt1[4 * 128 * 64];
__device__ __half g_bt2[4 * 64 * 64];
__device__ float g_sum[2 * C];
__device__ float g_sumsq[2 * C];

// ================= helpers =================
__device__ __forceinline__ void half_store4(float4 v, __half* pf) {
    __half2 a = __floats2half2_rn(v.x, v.y);
    __half2 b = __floats2half2_rn(v.z, v.w);
    *(uint2*)pf = make_uint2(*(uint32_t*)&a, *(uint32_t*)&b);
}
__device__ __forceinline__ float2 h2f2(uint32_t h) {
    return __half22float2(*(__half2*)&h);
}
__device__ __forceinline__ __half2 as_h2(int v) {
    return *(__half2*)&v;
}

// ================= B-tile fill helper =================
template <int NN>
__device__ __forceinline__ void bt_fill(int idx, const float* Wrel, const float* Wroot,
                                        __half* Bt) {
    int s = idx / (NN * 64);
    int r = idx % (NN * 64);
    int n = r / 64;
    int kk = r % 64;
    int path = s >> 1;
    int kh = s & 1;
    const float* W = path ? Wroot : Wrel;
    float w = W[(size_t)(kh * 64 + kk) * NN + n];
    Bt[(size_t)s * NN * 64 + n * 64 + kk] = __float2half_rn(w);
}

// ================= zero degree counters (tiny, first in graph) =================
__global__ void zero_cnt_kernel() {
    int i = blockIdx.x * blockDim.x + threadIdx.x;
    if (i < N_NODES) g_cnt[i] = 0;
    if (i < 2 * C) { g_sum[i] = 0.f; g_sumsq[i] = 0.f; }
}

// ================= setup: fp16 input + B tables =================
__global__ void setup_kernel(const float* __restrict__ x,
                             const float* __restrict__ Wr0, const float* __restrict__ Wo0,
                             const float* __restrict__ Wr1, const float* __restrict__ Wo1,
                             const float* __restrict__ Wr2, const float* __restrict__ Wo2) {
    int i = blockIdx.x * blockDim.x + threadIdx.x;
    if (i < N_NODES * (C / 4)) {
        float4 v = ((const float4*)x)[i];
        half_store4(v, g_xf + (size_t)i * 4);
    }
    const int B128 = 4 * 128 * 64;
    const int B64 = 4 * 64 * 64;
    if (i < B128) bt_fill<128>(i, Wr0, Wo0, g_bt0);
    else if (i < 2 * B128) bt_fill<128>(i - B128, Wr1, Wo1, g_bt1);
    else if (i < 2 * B128 + B64) bt_fill<64>(i - 2 * B128, Wr2, Wo2, g_bt2);
}

// ================= bucketed edge build: weight pre-converted to half2{w,w} =================
__global__ void build_kernel(const int* __restrict__ src,
                             const int* __restrict__ dst,
                             const float* __restrict__ w) {
    int e = blockIdx.x * blockDim.x + threadIdx.x;
    if (e < N_EDGES) {
        int d = dst[e];
        int p = atomicAdd(&g_cnt[d], 1);
        if (p < BUCKET) {
            __half2 wh = __half2half2(__float2half_rn(w[e]));
            g_edge[(size_t)d * BUCKET + p] = make_int2(src[e], *(int*)&wh);
        }
    }
}

// ================= aggregation: one warp/node, half2 chunk-4 accumulation =================
__global__ void aggregate_kernel() {
    int gw = (blockIdx.x * blockDim.x + threadIdx.x) >> 5;
    int lane = threadIdx.x & 31;
    if (gw >= N_NODES) return;
    int cnt = min(g_cnt[gw], BUCKET);
    const int2* eb = g_edge + (size_t)gw * BUCKET;
    const int4* eb4 = (const int4*)eb;   // 1024B-aligned base, j steps by 4
    float4 acc = make_float4(0.f, 0.f, 0.f, 0.f);
    const __half* xf = g_xf;
    int j = 0;
    for (; j + 3 < cnt; j += 4) {
        int4 p0 = eb4[(j >> 1) + 0];     // edges j, j+1
        int4 p1 = eb4[(j >> 1) + 1];     // edges j+2, j+3
        uint2 r0 = __ldg((const uint2*)(xf + (size_t)p0.x * C) + lane);
        uint2 r1 = __ldg((const uint2*)(xf + (size_t)p0.z * C) + lane);
        uint2 r2 = __ldg((const uint2*)(xf + (size_t)p1.x * C) + lane);
        uint2 r3 = __ldg((const uint2*)(xf + (size_t)p1.z * C) + lane);
        __half2 w0 = as_h2(p0.y), w1 = as_h2(p0.w);
        __half2 w2 = as_h2(p1.y), w3 = as_h2(p1.w);
        __half2 pa = __hmul2(as_h2(r0.x), w0);
        __half2 pb = __hmul2(as_h2(r0.y), w0);
        pa = __hfma2(as_h2(r1.x), w1, pa); pb = __hfma2(as_h2(r1.y), w1, pb);
        pa = __hfma2(as_h2(r2.x), w2, pa); pb = __hfma2(as_h2(r2.y), w2, pb);
        pa = __hfma2(as_h2(r3.x), w3, pa); pb = __hfma2(as_h2(r3.y), w3, pb);
        float2 fa = __half22float2(pa), fb = __half22float2(pb);
        acc.x += fa.x; acc.y += fa.y; acc.z += fb.x; acc.w += fb.y;
    }
    for (; j < cnt; j++) {
        int2 ed = eb[j];
        float w = __low2float(as_h2(ed.y));
        uint2 r = __ldg((const uint2*)(xf + (size_t)ed.x * C) + lane);
        float2 a = h2f2(r.x), b = h2f2(r.y);
        acc.x = fmaf(w, a.x, acc.x); acc.y = fmaf(w, a.y, acc.y);
        acc.z = fmaf(w, b.x, acc.z); acc.w = fmaf(w, b.y, acc.w);
    }
    half_store4(acc, g_aggf + (size_t)gw * C + lane * 4);
}

// ================= HMMA GEMM (templated pipeline) =================
// NIT iters of K=64: As = (it>>1) ? A1 : A0, kh = it&1; B slice = it.
template <int NN, int NIT, bool STATS, bool HALF_OUT>
__global__ void __launch_bounds__(256) mma_gemm_kernel(
    const __half* __restrict__ A0, const __half* __restrict__ A1,
    const __half* __restrict__ Bt,
    const float* __restrict__ bias, void* __restrict__ Hout, int layer) {
    constexpr int WM = (NN == 128) ? 2 : 4;
    constexpr int WN = 8 / WM;
    constexpr int MF = 128 / (WM * 16);
    constexpr int NF = NN / (WN * 8);
    constexpr int PITCH = 144;
    constexpr int ABYTES = 128 * PITCH;

    extern __shared__ __align__(16) char smem[];
    const uint32_t sb = smem_u32(smem);
    const uint32_t sA[2] = {sb, sb + ABYTES};
    const uint32_t sB[2] = {sb + 2 * ABYTES, sb + 2 * ABYTES + (uint32_t)(NN * PITCH)};
    __shared__ float ssum[NN], ssq[NN];

    const int tid = threadIdx.x;
    const int wid = tid >> 5;
    const int lane = tid & 31;
    const int m0 = blockIdx.x * 128;
    const int wmb = (wid / WN) * (MF * 16);
    const int wnb = (wid % WN) * (NF * 8);

    float acc[MF][NF][4];
    #pragma unroll
    for (int i = 0; i < MF; i++)
        #pragma unroll
        for (int j = 0; j < NF; j++)
            #pragma unroll
            for (int k = 0; k < 4; k++) acc[i][j][k] = 0.f;

    auto load_tile = [&](int it) {
        int buf = it & 1;
        const __half* As = (it >> 1) ? A1 : A0;
        int kh = it & 1;
        #pragma unroll
        for (int u = 0; u < 4; u++) {
            int unit = tid + u * 256;
            int row = unit >> 3, cu = unit & 7;
            int m = m0 + row;
            cpa16(sA[buf] + row * PITCH + cu * 16,
                  (const char*)(As + (size_t)m * C + kh * 64) + cu * 16,
                  (m < N_NODES) ? 16u : 0u);
        }
        const char* Bs = (const char*)(Bt + (size_t)it * NN * 64);
        #pragma unroll
        for (int u = 0; u < NN / 32; u++) {
            int unit = tid + u * 256;
            int n = unit >> 3, cu = unit & 7;
            cpa16(sB[buf] + n * PITCH + cu * 16, Bs + n * 128 + cu * 16, 16u);
        }
    };

    const uint32_t a_lane = (lane & 7) * PITCH + ((lane >> 3) & 1) * 8 * PITCH + (lane >> 4) * 16;
    const uint32_t b_lane = (lane & 7) * PITCH + (((lane & 15) >> 3)) * 16;

    load_tile(0);
    CP_COMMIT();
    for (int it = 0; it < NIT; it++) {
        if (it < NIT - 1) {
            load_tile(it + 1);
            CP_COMMIT();
            asm volatile("cp.async.wait_group 1;" ::: "memory");
        } else {
            asm volatile("cp.async.wait_group 0;" ::: "memory");
        }
        __syncthreads();
        uint32_t abase = sA[it & 1] + wmb * PITCH + a_lane;
        uint32_t bbase = sB[it & 1] + wnb * PITCH + b_lane;
        #pragma unroll
        for (int ks = 0; ks < 4; ks++) {
            uint32_t a[MF][4], b[NF][2];
            #pragma unroll
            for (int mf = 0; mf < MF; mf++) ldsm_x4(a[mf], abase + mf * 16 * PITCH + ks * 32);
            #pragma unroll
            for (int nf = 0; nf < NF; nf++) ldsm_x2(b[nf], bbase + nf * 8 * PITCH + ks * 32);
            #pragma unroll
            for (int mf = 0; mf < MF; mf++)
                #pragma unroll
                for (int nf = 0; nf < NF; nf++) mma16816(acc[mf][nf], a[mf], b[nf]);
        }
        __syncthreads();
    }

    if (STATS) {
        if (tid < NN) { ssum[tid] = 0.f; ssq[tid] = 0.f; }
        __syncthreads();
    }

    #pragma unroll
    for (int mf = 0; mf < MF; mf++) {
        int r = m0 + wmb + mf * 16 + (lane >> 2);
        #pragma unroll
        for (int nf = 0; nf < NF; nf++) {
            int cc = wnb + nf * 8 + (lane & 3) * 2;
            float b0 = bias ? bias[cc] : 0.f;
            float b1 = bias ? bias[cc + 1] : 0.f;
            float v0 = acc[mf][nf][0] + b0, v1 = acc[mf][nf][1] + b1;
            float v2 = acc[mf][nf][2] + b0, v3 = acc[mf][nf][3] + b1;
            if (HALF_OUT) {
                __half* H = (__half*)Hout;
                if (r < N_NODES) {
                    __half2 p = __floats2half2_rn(v0, v1);
                    *(uint32_t*)(H + (size_t)r * NN + cc) = *(uint32_t*)&p;
                }
                if (r + 8 < N_NODES) {
                    __half2 p = __floats2half2_rn(v2, v3);
                    *(uint32_t*)(H + (size_t)(r + 8) * NN + cc) = *(uint32_t*)&p;
                }
            } else {
                float* H = (float*)Hout;
                if (r < N_NODES)
                    *(float2*)(H + (size_t)r * NN + cc) = make_float2(v0, v1);
                if (r + 8 < N_NODES)
                    *(float2*)(H + (size_t)(r + 8) * NN + cc) = make_float2(v2, v3);
            }
        }
    }

    if (STATS) {
        // OOB rows hold zeros (cp.async zfill) -> contribute nothing
        #pragma unroll
        for (int nf = 0; nf < NF; nf++) {
            #pragma unroll
            for (int j = 0; j < 2; j++) {
                int col = wnb + nf * 8 + (lane & 3) * 2 + j;
                float s = 0.f, q = 0.f;
                #pragma unroll
                for (int mf = 0; mf < MF; mf++) {
                    float v0 = acc[mf][nf][j];
                    float v1 = acc[mf][nf][2 + j];
                    s += v0 + v1;
                    q += v0 * v0 + v1 * v1;
                }
                atomicAdd(&ssum[col], s);
                atomicAdd(&ssq[col], q);
            }
        }
        __syncthreads();
        if (tid < NN) {
            atomicAdd(&g_sum[layer * C + tid], ssum[tid]);
            atomicAdd(&g_sumsq[layer * C + tid], ssq[tid]);
        }
    }
}

// ================= BN apply (finalize fused): fp16 h in, fp16 x out =================
__global__ void bn_apply_kernel(const float* __restrict__ gamma,
                                const float* __restrict__ beta, int layer) {
    int i = blockIdx.x * blockDim.x + threadIdx.x;
    if (i >= N_NODES * (C / 4)) return;
    int c = (i & 31) << 2;
    float4 sm = *(const float4*)(g_sum + layer * C + c);
    float4 sq = *(const float4*)(g_sumsq + layer * C + c);
    float4 gm = *(const float4*)(gamma + c);
    float4 bt = *(const float4*)(beta + c);
    const float inv = 1.f / N_NODES;
    float mx = sm.x * inv, my = sm.y * inv, mz = sm.z * inv, mw = sm.w * inv;
    float scx = gm.x * rsqrtf(sq.x * inv - mx * mx + BN_EPS);
    float scy = gm.y * rsqrtf(sq.y * inv - my * my + BN_EPS);
    float scz = gm.z * rsqrtf(sq.z * inv - mz * mz + BN_EPS);
    float scw = gm.w * rsqrtf(sq.w * inv - mw * mw + BN_EPS);
    float shx = bt.x - mx * scx, shy = bt.y - my * scy;
    float shz = bt.z - mz * scz, shw = bt.w - mw * scw;

    uint2 hr = *(const uint2*)(g_hf + (size_t)i * 4);
    float2 ha = h2f2(hr.x), hb = h2f2(hr.y);
    uint2 xr = *(const uint2*)(g_xf + (size_t)i * 4);
    float2 xa = h2f2(xr.x), xb = h2f2(xr.y);
    float4 o;
    o.x = fmaxf(fmaf(ha.x, scx, shx) + xa.x, 0.f);
    o.y = fmaxf(fmaf(ha.y, scy, shy) + xa.y, 0.f);
    o.z = fmaxf(fmaf(hb.x, scz, shz) + xb.x, 0.f);
    o.w = fmaxf(fmaf(hb.y, scw, shw) + xb.y, 0.f);
    half_store4(o, g_xf + (size_t)i * 4);
}

// ================= launch =================
extern "C" void kernel_launch(void* const* d_in, const int* in_sizes, int n_in,
                              void* d_out, int out_size) {
    const float* x    = (const float*)d_in[0];
    const int*   esrc = (const int*)d_in[1];
    const int*   edst = (const int*)d_in[2];
    const float* ew   = (const float*)d_in[3];
    const float* Wr0  = (const float*)d_in[4];
    // b_rel0 (d_in[5]) cancels exactly under BN
    const float* Wo0  = (const float*)d_in[6];
    const float* Wr1  = (const float*)d_in[7];
    // b_rel1 (d_in[8]) cancels under BN
    const float* Wo1  = (const float*)d_in[9];
    const float* Wr2  = (const float*)d_in[10];
    const float* b2   = (const float*)d_in[11];
    const float* Wo2  = (const float*)d_in[12];
    const float* gamma0 = (const float*)d_in[13];
    const float* beta0  = (const float*)d_in[14];
    const float* gamma1 = (const float*)d_in[15];
    const float* beta1  = (const float*)d_in[16];
    float* out = (float*)d_out;

    __half *aggf, *xf, *hf, *bt0, *bt1, *bt2;
    cudaGetSymbolAddress((void**)&hf, g_hf);
    cudaGetSymbolAddress((void**)&aggf, g_aggf);
    cudaGetSymbolAddress((void**)&xf, g_xf);
    cudaGetSymbolAddress((void**)&bt0, g_bt0);
    cudaGetSymbolAddress((void**)&bt1, g_bt1);
    cudaGetSymbolAddress((void**)&bt2, g_bt2);

    const int SMEM128 = 2 * 128 * 144 + 2 * 128 * 144;  // 73728
    const int SMEM64  = 2 * 128 * 144 + 2 * 64 * 144;   // 55296
    cudaFuncSetAttribute((const void*)mma_gemm_kernel<128, 4, true, true>,
                         cudaFuncAttributeMaxDynamicSharedMemorySize, SMEM128);
    cudaFuncSetAttribute((const void*)mma_gemm_kernel<64, 4, false, false>,
                         cudaFuncAttributeMaxDynamicSharedMemorySize, SMEM64);

    const int EB = (N_EDGES + 255) / 256;
    const int AGG_B = (N_NODES + 7) / 8;
    const int GEMM_B = (N_NODES + 127) / 128;
    const int APPLY_B = (N_NODES * (C / 4) + 255) / 256;

    zero_cnt_kernel<<<(N_NODES + 255) / 256, 256>>>();
    build_kernel<<<EB, 256>>>(esrc, edst, ew);
    setup_kernel<<<APPLY_B, 256>>>(x, Wr0, Wo0, Wr1, Wo1, Wr2, Wo2);

    // ---- layer 0 ----
    aggregate_kernel<<<AGG_B, 256>>>();
    mma_gemm_kernel<128, 4, true, true><<<GEMM_B, 256, SMEM128>>>(
        aggf, xf, bt0, nullptr, hf, 0);
    bn_apply_kernel<<<APPLY_B, 256>>>(gamma0, beta0, 0);

    // ---- layer 1 ----
    aggregate_kernel<<<AGG_B, 256>>>();
    mma_gemm_kernel<128, 4, true, true><<<GEMM_B, 256, SMEM128>>>(
        aggf, xf, bt1, nullptr, hf, 1);
    bn_apply_kernel<<<APPLY_B, 256>>>(gamma1, beta1, 1);

    // ---- layer 2 ----
    aggregate_kernel<<<AGG_B, 256>>>();
    mma_gemm_kernel<64, 4, false, false><<<GEMM_B, 256, SMEM64>>>(
        aggf, xf, bt2, b2, out, 0);
}

// round 15
// speedup vs baseline: 1.0182x; 1.0182x over previous
#include <cuda_runtime.h>
#include <cuda_fp16.h>
#include <cstdint>

#define N_NODES 50000
#define N_EDGES 800000
#define C 128
#define BUCKET 128
#define BN_EPS 1e-5f

// ================= PTX helpers (sm_100-safe: mma.sync / ldmatrix / cp.async) =================
__device__ __forceinline__ uint32_t smem_u32(const void* p) {
    uint32_t a;
    asm("{ .reg .u64 t; cvta.to.shared.u64 t, %1; cvt.u32.u64 %0, t; }" : "=r"(a) : "l"(p));
    return a;
}
__device__ __forceinline__ void cpa16(uint32_t dst, const void* src, uint32_t sz) {
    asm volatile("cp.async.cg.shared.global [%0], [%1], 16, %2;" :: "r"(dst), "l"(src), "r"(sz));
}
#define CP_COMMIT() asm volatile("cp.async.commit_group;" ::: "memory")
__device__ __forceinline__ void ldsm_x4(uint32_t* r, uint32_t a) {
    asm volatile("ldmatrix.sync.aligned.m8n8.x4.shared.b16 {%0,%1,%2,%3}, [%4];"
                 : "=r"(r[0]), "=r"(r[1]), "=r"(r[2]), "=r"(r[3]) : "r"(a));
}
__device__ __forceinline__ void ldsm_x2(uint32_t* r, uint32_t a) {
    asm volatile("ldmatrix.sync.aligned.m8n8.x2.shared.b16 {%0,%1}, [%2];"
                 : "=r"(r[0]), "=r"(r[1]) : "r"(a));
}
__device__ __forceinline__ void mma16816(float* d, const uint32_t* a, const uint32_t* b) {
    asm volatile(
        "mma.sync.aligned.m16n8k16.row.col.f32.f16.f16.f32 "
        "{%0,%1,%2,%3},{%4,%5,%6,%7},{%8,%9},{%0,%1,%2,%3};"
        : "+f"(d[0]), "+f"(d[1]), "+f"(d[2]), "+f"(d[3])
        : "r"(a[0]), "r"(a[1]), "r"(a[2]), "r"(a[3]), "r"(b[0]), "r"(b[1]));
}

// ================= scratch =================
__device__ int   g_cnt[N_NODES];                       // per-node degree counter
__device__ int2  g_edge[(size_t)N_NODES * BUCKET];     // bucketed edges (src, weight-bits)
__device__ __half g_hf[N_NODES * C];     // fp16 pre-BN activations (layers 0/1)
__device__ __half g_xf[N_NODES * C];     // fp16 features (gather + GEMM X operand + residual)
__device__ __half g_aggf[N_NODES * C];   // fp16 aggregation result (GEMM A operand)
// B slices per layer: id = path*2 + khalf -> 4 slices of [NN][64] fp16 (W-hi only)
__device__ __half g_bt0[4 * 128 * 64];
__device__ __half g_bt1[4 * 128 * 64];
__device__ __half g_bt2[4 * 64 * 64];
__device__ float g_sum[2 * C];
__device__ float g_sumsq[2 * C];

// ================= helpers =================
__device__ __forceinline__ void half_store4(float4 v, __half* pf) {
    __half2 a = __floats2half2_rn(v.x, v.y);
    __half2 b = __floats2half2_rn(v.z, v.w);
    *(uint2*)pf = make_uint2(*(uint32_t*)&a, *(uint32_t*)&b);
}
__device__ __forceinline__ float2 h2f2(uint32_t h) {
    return __half22float2(*(__half2*)&h);
}

// ================= B-tile fill helper =================
template <int NN>
__device__ __forceinline__ void bt_fill(int idx, const float* Wrel, const float* Wroot,
                                        __half* Bt) {
    int s = idx / (NN * 64);
    int r = idx % (NN * 64);
    int n = r / 64;
    int kk = r % 64;
    int path = s >> 1;
    int kh = s & 1;
    const float* W = path ? Wroot : Wrel;
    float w = W[(size_t)(kh * 64 + kk) * NN + n];
    Bt[(size_t)s * NN * 64 + n * 64 + kk] = __float2half_rn(w);
}

// ================= setup: fp16 input + B tables + BN stat zero =================
__global__ void setup_kernel(const float* __restrict__ x,
                             const float* __restrict__ Wr0, const float* __restrict__ Wo0,
                             const float* __restrict__ Wr1, const float* __restrict__ Wo1,
                             const float* __restrict__ Wr2, const float* __restrict__ Wo2) {
    int i = blockIdx.x * blockDim.x + threadIdx.x;
    if (i < 2 * C) { g_sum[i] = 0.f; g_sumsq[i] = 0.f; }
    if (i < N_NODES * (C / 4)) {
        float4 v = ((const float4*)x)[i];
        half_store4(v, g_xf + (size_t)i * 4);
    }
    const int B128 = 4 * 128 * 64;
    const int B64 = 4 * 64 * 64;
    if (i < B128) bt_fill<128>(i, Wr0, Wo0, g_bt0);
    else if (i < 2 * B128) bt_fill<128>(i - B128, Wr1, Wo1, g_bt1);
    else if (i < 2 * B128 + B64) bt_fill<64>(i - 2 * B128, Wr2, Wo2, g_bt2);
}

// ================= bucketed edge build: one pass, no hist/scan =================
__global__ void build_kernel(const int* __restrict__ src,
                             const int* __restrict__ dst,
                             const float* __restrict__ w) {
    int e = blockIdx.x * blockDim.x + threadIdx.x;
    if (e < N_EDGES) {
        int d = dst[e];
        int p = atomicAdd(&g_cnt[d], 1);
        if (p < BUCKET)
            g_edge[(size_t)d * BUCKET + p] = make_int2(src[e], __float_as_int(w[e]));
    }
}

// ================= aggregation: one warp/node, fp16 gather, unroll 8 =================
__global__ void aggregate_kernel() {
    int gw = (blockIdx.x * blockDim.x + threadIdx.x) >> 5;
    int lane = threadIdx.x & 31;
    if (gw >= N_NODES) return;
    int cnt = min(g_cnt[gw], BUCKET);
    const int2* eb = g_edge + (size_t)gw * BUCKET;
    float4 acc = make_float4(0.f, 0.f, 0.f, 0.f);
    const __half* xf = g_xf;
    int j = 0;
    for (; j + 7 < cnt; j += 8) {
        int2 ed[8];
        uint2 r[8];
        #pragma unroll
        for (int u = 0; u < 8; u++) ed[u] = eb[j + u];
        #pragma unroll
        for (int u = 0; u < 8; u++)
            r[u] = __ldg((const uint2*)(xf + (size_t)ed[u].x * C) + lane);
        #pragma unroll
        for (int u = 0; u < 8; u++) {
            float w = __int_as_float(ed[u].y);
            float2 a = h2f2(r[u].x), b = h2f2(r[u].y);
            acc.x = fmaf(w, a.x, acc.x); acc.y = fmaf(w, a.y, acc.y);
            acc.z = fmaf(w, b.x, acc.z); acc.w = fmaf(w, b.y, acc.w);
        }
    }
    for (; j + 3 < cnt; j += 4) {
        int2 e0 = eb[j], e1 = eb[j + 1], e2 = eb[j + 2], e3 = eb[j + 3];
        uint2 r0 = __ldg((const uint2*)(xf + (size_t)e0.x * C) + lane);
        uint2 r1 = __ldg((const uint2*)(xf + (size_t)e1.x * C) + lane);
        uint2 r2 = __ldg((const uint2*)(xf + (size_t)e2.x * C) + lane);
        uint2 r3 = __ldg((const uint2*)(xf + (size_t)e3.x * C) + lane);
        float w0 = __int_as_float(e0.y), w1 = __int_as_float(e1.y);
        float w2 = __int_as_float(e2.y), w3 = __int_as_float(e3.y);
        float2 a, b;
        a = h2f2(r0.x); b = h2f2(r0.y);
        acc.x = fmaf(w0, a.x, acc.x); acc.y = fmaf(w0, a.y, acc.y);
        acc.z = fmaf(w0, b.x, acc.z); acc.w = fmaf(w0, b.y, acc.w);
        a = h2f2(r1.x); b = h2f2(r1.y);
        acc.x = fmaf(w1, a.x, acc.x); acc.y = fmaf(w1, a.y, acc.y);
        acc.z = fmaf(w1, b.x, acc.z); acc.w = fmaf(w1, b.y, acc.w);
        a = h2f2(r2.x); b = h2f2(r2.y);
        acc.x = fmaf(w2, a.x, acc.x); acc.y = fmaf(w2, a.y, acc.y);
        acc.z = fmaf(w2, b.x, acc.z); acc.w = fmaf(w2, b.y, acc.w);
        a = h2f2(r3.x); b = h2f2(r3.y);
        acc.x = fmaf(w3, a.x, acc.x); acc.y = fmaf(w3, a.y, acc.y);
        acc.z = fmaf(w3, b.x, acc.z); acc.w = fmaf(w3, b.y, acc.w);
    }
    for (; j < cnt; j++) {
        int2 ed = eb[j];
        float w = __int_as_float(ed.y);
        uint2 r = __ldg((const uint2*)(xf + (size_t)ed.x * C) + lane);
        float2 a = h2f2(r.x), b = h2f2(r.y);
        acc.x = fmaf(w, a.x, acc.x); acc.y = fmaf(w, a.y, acc.y);
        acc.z = fmaf(w, b.x, acc.z); acc.w = fmaf(w, b.y, acc.w);
    }
    half_store4(acc, g_aggf + (size_t)gw * C + lane * 4);
}

// ================= HMMA GEMM (templated pipeline) =================
// NIT iters of K=64: As = (it>>1) ? A1 : A0, kh = it&1; B slice = it.
template <int NN, int NIT, bool STATS, bool HALF_OUT>
__global__ void __launch_bounds__(256) mma_gemm_kernel(
    const __half* __restrict__ A0, const __half* __restrict__ A1,
    const __half* __restrict__ Bt,
    const float* __restrict__ bias, void* __restrict__ Hout, int layer) {
    constexpr int WM = (NN == 128) ? 2 : 4;
    constexpr int WN = 8 / WM;
    constexpr int MF = 128 / (WM * 16);
    constexpr int NF = NN / (WN * 8);
    constexpr int PITCH = 144;
    constexpr int ABYTES = 128 * PITCH;

    extern __shared__ __align__(16) char smem[];
    const uint32_t sb = smem_u32(smem);
    const uint32_t sA[2] = {sb, sb + ABYTES};
    const uint32_t sB[2] = {sb + 2 * ABYTES, sb + 2 * ABYTES + (uint32_t)(NN * PITCH)};
    __shared__ float ssum[NN], ssq[NN];

    const int tid = threadIdx.x;
    const int wid = tid >> 5;
    const int lane = tid & 31;
    const int m0 = blockIdx.x * 128;
    const int wmb = (wid / WN) * (MF * 16);
    const int wnb = (wid % WN) * (NF * 8);

    float acc[MF][NF][4];
    #pragma unroll
    for (int i = 0; i < MF; i++)
        #pragma unroll
        for (int j = 0; j < NF; j++)
            #pragma unroll
            for (int k = 0; k < 4; k++) acc[i][j][k] = 0.f;

    auto load_tile = [&](int it) {
        int buf = it & 1;
        const __half* As = (it >> 1) ? A1 : A0;
        int kh = it & 1;
        #pragma unroll
        for (int u = 0; u < 4; u++) {
            int unit = tid + u * 256;
            int row = unit >> 3, cu = unit & 7;
            int m = m0 + row;
            cpa16(sA[buf] + row * PITCH + cu * 16,
                  (const char*)(As + (size_t)m * C + kh * 64) + cu * 16,
                  (m < N_NODES) ? 16u : 0u);
        }
        const char* Bs = (const char*)(Bt + (size_t)it * NN * 64);
        #pragma unroll
        for (int u = 0; u < NN / 32; u++) {
            int unit = tid + u * 256;
            int n = unit >> 3, cu = unit & 7;
            cpa16(sB[buf] + n * PITCH + cu * 16, Bs + n * 128 + cu * 16, 16u);
        }
    };

    const uint32_t a_lane = (lane & 7) * PITCH + ((lane >> 3) & 1) * 8 * PITCH + (lane >> 4) * 16;
    const uint32_t b_lane = (lane & 7) * PITCH + (((lane & 15) >> 3)) * 16;

    load_tile(0);
    CP_COMMIT();
    for (int it = 0; it < NIT; it++) {
        if (it < NIT - 1) {
            load_tile(it + 1);
            CP_COMMIT();
            asm volatile("cp.async.wait_group 1;" ::: "memory");
        } else {
            asm volatile("cp.async.wait_group 0;" ::: "memory");
        }
        __syncthreads();
        uint32_t abase = sA[it & 1] + wmb * PITCH + a_lane;
        uint32_t bbase = sB[it & 1] + wnb * PITCH + b_lane;
        #pragma unroll
        for (int ks = 0; ks < 4; ks++) {
            uint32_t a[MF][4], b[NF][2];
            #pragma unroll
            for (int mf = 0; mf < MF; mf++) ldsm_x4(a[mf], abase + mf * 16 * PITCH + ks * 32);
            #pragma unroll
            for (int nf = 0; nf < NF; nf++) ldsm_x2(b[nf], bbase + nf * 8 * PITCH + ks * 32);
            #pragma unroll
            for (int mf = 0; mf < MF; mf++)
                #pragma unroll
                for (int nf = 0; nf < NF; nf++) mma16816(acc[mf][nf], a[mf], b[nf]);
        }
        __syncthreads();
    }

    if (STATS) {
        if (tid < NN) { ssum[tid] = 0.f; ssq[tid] = 0.f; }
        __syncthreads();
    }

    #pragma unroll
    for (int mf = 0; mf < MF; mf++) {
        int r = m0 + wmb + mf * 16 + (lane >> 2);
        #pragma unroll
        for (int nf = 0; nf < NF; nf++) {
            int cc = wnb + nf * 8 + (lane & 3) * 2;
            float b0 = bias ? bias[cc] : 0.f;
            float b1 = bias ? bias[cc + 1] : 0.f;
            float v0 = acc[mf][nf][0] + b0, v1 = acc[mf][nf][1] + b1;
            float v2 = acc[mf][nf][2] + b0, v3 = acc[mf][nf][3] + b1;
            if (HALF_OUT) {
                __half* H = (__half*)Hout;
                if (r < N_NODES) {
                    __half2 p = __floats2half2_rn(v0, v1);
                    *(uint32_t*)(H + (size_t)r * NN + cc) = *(uint32_t*)&p;
                }
                if (r + 8 < N_NODES) {
                    __half2 p = __floats2half2_rn(v2, v3);
                    *(uint32_t*)(H + (size_t)(r + 8) * NN + cc) = *(uint32_t*)&p;
                }
            } else {
                float* H = (float*)Hout;
                if (r < N_NODES)
                    *(float2*)(H + (size_t)r * NN + cc) = make_float2(v0, v1);
                if (r + 8 < N_NODES)
                    *(float2*)(H + (size_t)(r + 8) * NN + cc) = make_float2(v2, v3);
            }
        }
    }

    if (STATS) {
        // OOB rows hold zeros (cp.async zfill) -> contribute nothing
        #pragma unroll
        for (int nf = 0; nf < NF; nf++) {
            #pragma unroll
            for (int j = 0; j < 2; j++) {
                int col = wnb + nf * 8 + (lane & 3) * 2 + j;
                float s = 0.f, q = 0.f;
                #pragma unroll
                for (int mf = 0; mf < MF; mf++) {
                    float v0 = acc[mf][nf][j];
                    float v1 = acc[mf][nf][2 + j];
                    s += v0 + v1;
                    q += v0 * v0 + v1 * v1;
                }
                atomicAdd(&ssum[col], s);
                atomicAdd(&ssq[col], q);
            }
        }
        __syncthreads();
        if (tid < NN) {
            atomicAdd(&g_sum[layer * C + tid], ssum[tid]);
            atomicAdd(&g_sumsq[layer * C + tid], ssq[tid]);
        }
    }
}

// ================= BN apply (finalize fused): fp16 h in, fp16 x out =================
__global__ void bn_apply_kernel(const float* __restrict__ gamma,
                                const float* __restrict__ beta, int layer) {
    int i = blockIdx.x * blockDim.x + threadIdx.x;
    if (i >= N_NODES * (C / 4)) return;
    int c = (i & 31) << 2;
    float4 sm = *(const float4*)(g_sum + layer * C + c);
    float4 sq = *(const float4*)(g_sumsq + layer * C + c);
    float4 gm = *(const float4*)(gamma + c);
    float4 bt = *(const float4*)(beta + c);
    const float inv = 1.f / N_NODES;
    float mx = sm.x * inv, my = sm.y * inv, mz = sm.z * inv, mw = sm.w * inv;
    float scx = gm.x * rsqrtf(sq.x * inv - mx * mx + BN_EPS);
    float scy = gm.y * rsqrtf(sq.y * inv - my * my + BN_EPS);
    float scz = gm.z * rsqrtf(sq.z * inv - mz * mz + BN_EPS);
    float scw = gm.w * rsqrtf(sq.w * inv - mw * mw + BN_EPS);
    float shx = bt.x - mx * scx, shy = bt.y - my * scy;
    float shz = bt.z - mz * scz, shw = bt.w - mw * scw;

    uint2 hr = *(const uint2*)(g_hf + (size_t)i * 4);
    float2 ha = h2f2(hr.x), hb = h2f2(hr.y);
    uint2 xr = *(const uint2*)(g_xf + (size_t)i * 4);
    float2 xa = h2f2(xr.x), xb = h2f2(xr.y);
    float4 o;
    o.x = fmaxf(fmaf(ha.x, scx, shx) + xa.x, 0.f);
    o.y = fmaxf(fmaf(ha.y, scy, shy) + xa.y, 0.f);
    o.z = fmaxf(fmaf(hb.x, scz, shz) + xb.x, 0.f);
    o.w = fmaxf(fmaf(hb.y, scw, shw) + xb.y, 0.f);
    half_store4(o, g_xf + (size_t)i * 4);
}

// ================= launch =================
extern "C" void kernel_launch(void* const* d_in, const int* in_sizes, int n_in,
                              void* d_out, int out_size) {
    const float* x    = (const float*)d_in[0];
    const int*   esrc = (const int*)d_in[1];
    const int*   edst = (const int*)d_in[2];
    const float* ew   = (const float*)d_in[3];
    const float* Wr0  = (const float*)d_in[4];
    // b_rel0 (d_in[5]) cancels exactly under BN
    const float* Wo0  = (const float*)d_in[6];
    const float* Wr1  = (const float*)d_in[7];
    // b_rel1 (d_in[8]) cancels under BN
    const float* Wo1  = (const float*)d_in[9];
    const float* Wr2  = (const float*)d_in[10];
    const float* b2   = (const float*)d_in[11];
    const float* Wo2  = (const float*)d_in[12];
    const float* gamma0 = (const float*)d_in[13];
    const float* beta0  = (const float*)d_in[14];
    const float* gamma1 = (const float*)d_in[15];
    const float* beta1  = (const float*)d_in[16];
    float* out = (float*)d_out;

    __half *aggf, *xf, *hf, *bt0, *bt1, *bt2;
    int* cnt;
    cudaGetSymbolAddress((void**)&cnt, g_cnt);
    cudaGetSymbolAddress((void**)&hf, g_hf);
    cudaGetSymbolAddress((void**)&aggf, g_aggf);
    cudaGetSymbolAddress((void**)&xf, g_xf);
    cudaGetSymbolAddress((void**)&bt0, g_bt0);
    cudaGetSymbolAddress((void**)&bt1, g_bt1);
    cudaGetSymbolAddress((void**)&bt2, g_bt2);

    const int SMEM128 = 2 * 128 * 144 + 2 * 128 * 144;  // 73728
    const int SMEM64  = 2 * 128 * 144 + 2 * 64 * 144;   // 55296
    cudaFuncSetAttribute((const void*)mma_gemm_kernel<128, 4, true, true>,
                         cudaFuncAttributeMaxDynamicSharedMemorySize, SMEM128);
    cudaFuncSetAttribute((const void*)mma_gemm_kernel<64, 4, false, false>,
                         cudaFuncAttributeMaxDynamicSharedMemorySize, SMEM64);

    const int EB = (N_EDGES + 255) / 256;
    const int AGG_B = (N_NODES + 7) / 8;
    const int GEMM_B = (N_NODES + 127) / 128;
    const int APPLY_B = (N_NODES * (C / 4) + 255) / 256;

    cudaMemsetAsync(cnt, 0, N_NODES * sizeof(int));
    build_kernel<<<EB, 256>>>(esrc, edst, ew);
    setup_kernel<<<APPLY_B, 256>>>(x, Wr0, Wo0, Wr1, Wo1, Wr2, Wo2);

    // ---- layer 0 ----
    aggregate_kernel<<<AGG_B, 256>>>();
    mma_gemm_kernel<128, 4, true, true><<<GEMM_B, 256, SMEM128>>>(
        aggf, xf, bt0, nullptr, hf, 0);
    bn_apply_kernel<<<APPLY_B, 256>>>(gamma0, beta0, 0);

    // ---- layer 1 ----
    aggregate_kernel<<<AGG_B, 256>>>();
    mma_gemm_kernel<128, 4, true, true><<<GEMM_B, 256, SMEM128>>>(
        aggf, xf, bt1, nullptr, hf, 1);
    bn_apply_kernel<<<APPLY_B, 256>>>(gamma1, beta1, 1);

    // ---- layer 2 ----
    aggregate_kernel<<<AGG_B, 256>>>();
    mma_gemm_kernel<64, 4, false, false><<<GEMM_B, 256, SMEM64>>>(
        aggf, xf, bt2, b2, out, 0);
}

// round 17
// speedup vs baseline: 1.1651x; 1.1443x over previous
#include <cuda_runtime.h>
#include <cuda_fp16.h>
#include <cstdint>

#define N_NODES 50000
#define N_EDGES 800000
#define C 128
#define BUCKET 128
#define BN_EPS 1e-5f

// ================= PTX helpers (sm_100-safe: mma.sync / ldmatrix / cp.async) =================
__device__ __forceinline__ uint32_t smem_u32(const void* p) {
    uint32_t a;
    asm("{ .reg .u64 t; cvta.to.shared.u64 t, %1; cvt.u32.u64 %0, t; }" : "=r"(a) : "l"(p));
    return a;
}
__device__ __forceinline__ void cpa16(uint32_t dst, const void* src, uint32_t sz) {
    asm volatile("cp.async.cg.shared.global [%0], [%1], 16, %2;" :: "r"(dst), "l"(src), "r"(sz));
}
#define CP_COMMIT() asm volatile("cp.async.commit_group;" ::: "memory")
__device__ __forceinline__ void ldsm_x4(uint32_t* r, uint32_t a) {
    asm volatile("ldmatrix.sync.aligned.m8n8.x4.shared.b16 {%0,%1,%2,%3}, [%4];"
                 : "=r"(r[0]), "=r"(r[1]), "=r"(r[2]), "=r"(r[3]) : "r"(a));
}
__device__ __forceinline__ void ldsm_x2(uint32_t* r, uint32_t a) {
    asm volatile("ldmatrix.sync.aligned.m8n8.x2.shared.b16 {%0,%1}, [%2];"
                 : "=r"(r[0]), "=r"(r[1]) : "r"(a));
}
__device__ __forceinline__ void mma16816(float* d, const uint32_t* a, const uint32_t* b) {
    asm volatile(
        "mma.sync.aligned.m16n8k16.row.col.f32.f16.f16.f32 "
        "{%0,%1,%2,%3},{%4,%5,%6,%7},{%8,%9},{%0,%1,%2,%3};"
        : "+f"(d[0]), "+f"(d[1]), "+f"(d[2]), "+f"(d[3])
        : "r"(a[0]), "r"(a[1]), "r"(a[2]), "r"(a[3]), "r"(b[0]), "r"(b[1]));
}

// ================= scratch =================
__device__ int   g_cnt[N_NODES];                       // per-node degree counter
__device__ int2  g_edge[(size_t)N_NODES * BUCKET];     // bucketed edges (src, weight-bits)
__device__ __half g_hf[N_NODES * C];     // fp16 pre-BN activations (layers 0/1)
__device__ __half g_xf[N_NODES * C];     // fp16 features (gather + GEMM X operand + residual)
__device__ __half g_aggf[N_NODES * C];   // fp16 aggregation result (GEMM A operand)
// B slices per layer: id = path*2 + khalf -> 4 slices of [NN][64] fp16 (W-hi only)
__device__ __half g_bt0[4 * 128 * 64];
__device__ __half g_bt1[4 * 128 * 64];
__device__ __half g_bt2[4 * 64 * 64];
__device__ float g_sum[2 * C];
__device__ float g_sumsq[2 * C];

// ================= helpers =================
__device__ __forceinline__ void half_store4(float4 v, __half* pf) {
    __half2 a = __floats2half2_rn(v.x, v.y);
    __half2 b = __floats2half2_rn(v.z, v.w);
    *(uint2*)pf = make_uint2(*(uint32_t*)&a, *(uint32_t*)&b);
}
__device__ __forceinline__ float2 h2f2(uint32_t h) {
    return __half22float2(*(__half2*)&h);
}

// ================= B-tile fill helper =================
template <int NN>
__device__ __forceinline__ void bt_fill(int idx, const float* Wrel, const float* Wroot,
                                        __half* Bt) {
    int s = idx / (NN * 64);
    int r = idx % (NN * 64);
    int n = r / 64;
    int kk = r % 64;
    int path = s >> 1;
    int kh = s & 1;
    const float* W = path ? Wroot : Wrel;
    float w = W[(size_t)(kh * 64 + kk) * NN + n];
    Bt[(size_t)s * NN * 64 + n * 64 + kk] = __float2half_rn(w);
}

// ================= setup: fp16 input + B tables + BN stat zero =================
__global__ void setup_kernel(const float* __restrict__ x,
                             const float* __restrict__ Wr0, const float* __restrict__ Wo0,
                             const float* __restrict__ Wr1, const float* __restrict__ Wo1,
                             const float* __restrict__ Wr2, const float* __restrict__ Wo2) {
    int i = blockIdx.x * blockDim.x + threadIdx.x;
    if (i < 2 * C) { g_sum[i] = 0.f; g_sumsq[i] = 0.f; }
    if (i < N_NODES * (C / 4)) {
        float4 v = ((const float4*)x)[i];
        half_store4(v, g_xf + (size_t)i * 4);
    }
    const int B128 = 4 * 128 * 64;
    const int B64 = 4 * 64 * 64;
    if (i < B128) bt_fill<128>(i, Wr0, Wo0, g_bt0);
    else if (i < 2 * B128) bt_fill<128>(i - B128, Wr1, Wo1, g_bt1);
    else if (i < 2 * B128 + B64) bt_fill<64>(i - 2 * B128, Wr2, Wo2, g_bt2);
}

// ================= bucketed edge build: one pass, no hist/scan =================
__global__ void build_kernel(const int* __restrict__ src,
                             const int* __restrict__ dst,
                             const float* __restrict__ w) {
    int e = blockIdx.x * blockDim.x + threadIdx.x;
    if (e < N_EDGES) {
        int d = dst[e];
        int p = atomicAdd(&g_cnt[d], 1);
        if (p < BUCKET)
            g_edge[(size_t)d * BUCKET + p] = make_int2(src[e], __float_as_int(w[e]));
    }
}

// ================= aggregation: one warp/node, fp16 gather (R13 proven form) =================
__global__ void aggregate_kernel() {
    int gw = (blockIdx.x * blockDim.x + threadIdx.x) >> 5;
    int lane = threadIdx.x & 31;
    if (gw >= N_NODES) return;
    int cnt = min(g_cnt[gw], BUCKET);
    const int2* eb = g_edge + (size_t)gw * BUCKET;
    float4 acc = make_float4(0.f, 0.f, 0.f, 0.f);
    const __half* xf = g_xf;
    int j = 0;
    for (; j + 3 < cnt; j += 4) {
        int2 e0 = eb[j], e1 = eb[j + 1], e2 = eb[j + 2], e3 = eb[j + 3];
        uint2 r0 = __ldg((const uint2*)(xf + (size_t)e0.x * C) + lane);
        uint2 r1 = __ldg((const uint2*)(xf + (size_t)e1.x * C) + lane);
        uint2 r2 = __ldg((const uint2*)(xf + (size_t)e2.x * C) + lane);
        uint2 r3 = __ldg((const uint2*)(xf + (size_t)e3.x * C) + lane);
        float w0 = __int_as_float(e0.y), w1 = __int_as_float(e1.y);
        float w2 = __int_as_float(e2.y), w3 = __int_as_float(e3.y);
        float2 a, b;
        a = h2f2(r0.x); b = h2f2(r0.y);
        acc.x = fmaf(w0, a.x, acc.x); acc.y = fmaf(w0, a.y, acc.y);
        acc.z = fmaf(w0, b.x, acc.z); acc.w = fmaf(w0, b.y, acc.w);
        a = h2f2(r1.x); b = h2f2(r1.y);
        acc.x = fmaf(w1, a.x, acc.x); acc.y = fmaf(w1, a.y, acc.y);
        acc.z = fmaf(w1, b.x, acc.z); acc.w = fmaf(w1, b.y, acc.w);
        a = h2f2(r2.x); b = h2f2(r2.y);
        acc.x = fmaf(w2, a.x, acc.x); acc.y = fmaf(w2, a.y, acc.y);
        acc.z = fmaf(w2, b.x, acc.z); acc.w = fmaf(w2, b.y, acc.w);
        a = h2f2(r3.x); b = h2f2(r3.y);
        acc.x = fmaf(w3, a.x, acc.x); acc.y = fmaf(w3, a.y, acc.y);
        acc.z = fmaf(w3, b.x, acc.z); acc.w = fmaf(w3, b.y, acc.w);
    }
    for (; j < cnt; j++) {
        int2 ed = eb[j];
        float w = __int_as_float(ed.y);
        uint2 r = __ldg((const uint2*)(xf + (size_t)ed.x * C) + lane);
        float2 a = h2f2(r.x), b = h2f2(r.y);
        acc.x = fmaf(w, a.x, acc.x); acc.y = fmaf(w, a.y, acc.y);
        acc.z = fmaf(w, b.x, acc.z); acc.w = fmaf(w, b.y, acc.w);
    }
    half_store4(acc, g_aggf + (size_t)gw * C + lane * 4);
}

// ================= HMMA GEMM (2 CTAs/SM forced) =================
// NIT iters of K=64: As = (it>>1) ? A1 : A0, kh = it&1; B slice = it.
template <int NN, int NIT, bool STATS, bool HALF_OUT>
__global__ void __launch_bounds__(256, 2) mma_gemm_kernel(
    const __half* __restrict__ A0, const __half* __restrict__ A1,
    const __half* __restrict__ Bt,
    const float* __restrict__ bias, void* __restrict__ Hout, int layer) {
    constexpr int WM = (NN == 128) ? 2 : 4;
    constexpr int WN = 8 / WM;
    constexpr int MF = 128 / (WM * 16);
    constexpr int NF = NN / (WN * 8);
    constexpr int PITCH = 144;
    constexpr int ABYTES = 128 * PITCH;

    extern __shared__ __align__(16) char smem[];
    const uint32_t sb = smem_u32(smem);
    const uint32_t sA[2] = {sb, sb + ABYTES};
    const uint32_t sB[2] = {sb + 2 * ABYTES, sb + 2 * ABYTES + (uint32_t)(NN * PITCH)};
    __shared__ float ssum[NN], ssq[NN];

    const int tid = threadIdx.x;
    const int wid = tid >> 5;
    const int lane = tid & 31;
    const int m0 = blockIdx.x * 128;
    const int wmb = (wid / WN) * (MF * 16);
    const int wnb = (wid % WN) * (NF * 8);

    float acc[MF][NF][4];
    #pragma unroll
    for (int i = 0; i < MF; i++)
        #pragma unroll
        for (int j = 0; j < NF; j++)
            #pragma unroll
            for (int k = 0; k < 4; k++) acc[i][j][k] = 0.f;

    auto load_tile = [&](int it) {
        int buf = it & 1;
        const __half* As = (it >> 1) ? A1 : A0;
        int kh = it & 1;
        #pragma unroll
        for (int u = 0; u < 4; u++) {
            int unit = tid + u * 256;
            int row = unit >> 3, cu = unit & 7;
            int m = m0 + row;
            cpa16(sA[buf] + row * PITCH + cu * 16,
                  (const char*)(As + (size_t)m * C + kh * 64) + cu * 16,
                  (m < N_NODES) ? 16u : 0u);
        }
        const char* Bs = (const char*)(Bt + (size_t)it * NN * 64);
        #pragma unroll
        for (int u = 0; u < NN / 32; u++) {
            int unit = tid + u * 256;
            int n = unit >> 3, cu = unit & 7;
            cpa16(sB[buf] + n * PITCH + cu * 16, Bs + n * 128 + cu * 16, 16u);
        }
    };

    const uint32_t a_lane = (lane & 7) * PITCH + ((lane >> 3) & 1) * 8 * PITCH + (lane >> 4) * 16;
    const uint32_t b_lane = (lane & 7) * PITCH + (((lane & 15) >> 3)) * 16;

    load_tile(0);
    CP_COMMIT();
    for (int it = 0; it < NIT; it++) {
        if (it < NIT - 1) {
            load_tile(it + 1);
            CP_COMMIT();
            asm volatile("cp.async.wait_group 1;" ::: "memory");
        } else {
            asm volatile("cp.async.wait_group 0;" ::: "memory");
        }
        __syncthreads();
        uint32_t abase = sA[it & 1] + wmb * PITCH + a_lane;
        uint32_t bbase = sB[it & 1] + wnb * PITCH + b_lane;
        #pragma unroll
        for (int ks = 0; ks < 4; ks++) {
            uint32_t a[MF][4], b[NF][2];
            #pragma unroll
            for (int mf = 0; mf < MF; mf++) ldsm_x4(a[mf], abase + mf * 16 * PITCH + ks * 32);
            #pragma unroll
            for (int nf = 0; nf < NF; nf++) ldsm_x2(b[nf], bbase + nf * 8 * PITCH + ks * 32);
            #pragma unroll
            for (int mf = 0; mf < MF; mf++)
                #pragma unroll
                for (int nf = 0; nf < NF; nf++) mma16816(acc[mf][nf], a[mf], b[nf]);
        }
        __syncthreads();
    }

    if (STATS) {
        if (tid < NN) { ssum[tid] = 0.f; ssq[tid] = 0.f; }
        __syncthreads();
    }

    #pragma unroll
    for (int mf = 0; mf < MF; mf++) {
        int r = m0 + wmb + mf * 16 + (lane >> 2);
        #pragma unroll
        for (int nf = 0; nf < NF; nf++) {
            int cc = wnb + nf * 8 + (lane & 3) * 2;
            float b0 = bias ? bias[cc] : 0.f;
            float b1 = bias ? bias[cc + 1] : 0.f;
            float v0 = acc[mf][nf][0] + b0, v1 = acc[mf][nf][1] + b1;
            float v2 = acc[mf][nf][2] + b0, v3 = acc[mf][nf][3] + b1;
            if (HALF_OUT) {
                __half* H = (__half*)Hout;
                if (r < N_NODES) {
                    __half2 p = __floats2half2_rn(v0, v1);
                    *(uint32_t*)(H + (size_t)r * NN + cc) = *(uint32_t*)&p;
                }
                if (r + 8 < N_NODES) {
                    __half2 p = __floats2half2_rn(v2, v3);
                    *(uint32_t*)(H + (size_t)(r + 8) * NN + cc) = *(uint32_t*)&p;
                }
            } else {
                float* H = (float*)Hout;
                if (r < N_NODES)
                    *(float2*)(H + (size_t)r * NN + cc) = make_float2(v0, v1);
                if (r + 8 < N_NODES)
                    *(float2*)(H + (size_t)(r + 8) * NN + cc) = make_float2(v2, v3);
            }
        }
    }

    if (STATS) {
        // OOB rows hold zeros (cp.async zfill) -> contribute nothing
        #pragma unroll
        for (int nf = 0; nf < NF; nf++) {
            #pragma unroll
            for (int j = 0; j < 2; j++) {
                int col = wnb + nf * 8 + (lane & 3) * 2 + j;
                float s = 0.f, q = 0.f;
                #pragma unroll
                for (int mf = 0; mf < MF; mf++) {
                    float v0 = acc[mf][nf][j];
                    float v1 = acc[mf][nf][2 + j];
                    s += v0 + v1;
                    q += v0 * v0 + v1 * v1;
                }
                atomicAdd(&ssum[col], s);
                atomicAdd(&ssq[col], q);
            }
        }
        __syncthreads();
        if (tid < NN) {
            atomicAdd(&g_sum[layer * C + tid], ssum[tid]);
            atomicAdd(&g_sumsq[layer * C + tid], ssq[tid]);
        }
    }
}

// ================= BN apply (finalize fused): fp16 h in, fp16 x out =================
__global__ void bn_apply_kernel(const float* __restrict__ gamma,
                                const float* __restrict__ beta, int layer) {
    int i = blockIdx.x * blockDim.x + threadIdx.x;
    if (i >= N_NODES * (C / 4)) return;
    int c = (i & 31) << 2;
    float4 sm = *(const float4*)(g_sum + layer * C + c);
    float4 sq = *(const float4*)(g_sumsq + layer * C + c);
    float4 gm = *(const float4*)(gamma + c);
    float4 bt = *(const float4*)(beta + c);
    const float inv = 1.f / N_NODES;
    float mx = sm.x * inv, my = sm.y * inv, mz = sm.z * inv, mw = sm.w * inv;
    float scx = gm.x * rsqrtf(sq.x * inv - mx * mx + BN_EPS);
    float scy = gm.y * rsqrtf(sq.y * inv - my * my + BN_EPS);
    float scz = gm.z * rsqrtf(sq.z * inv - mz * mz + BN_EPS);
    float scw = gm.w * rsqrtf(sq.w * inv - mw * mw + BN_EPS);
    float shx = bt.x - mx * scx, shy = bt.y - my * scy;
    float shz = bt.z - mz * scz, shw = bt.w - mw * scw;

    uint2 hr = *(const uint2*)(g_hf + (size_t)i * 4);
    float2 ha = h2f2(hr.x), hb = h2f2(hr.y);
    uint2 xr = *(const uint2*)(g_xf + (size_t)i * 4);
    float2 xa = h2f2(xr.x), xb = h2f2(xr.y);
    float4 o;
    o.x = fmaxf(fmaf(ha.x, scx, shx) + xa.x, 0.f);
    o.y = fmaxf(fmaf(ha.y, scy, shy) + xa.y, 0.f);
    o.z = fmaxf(fmaf(hb.x, scz, shz) + xb.x, 0.f);
    o.w = fmaxf(fmaf(hb.y, scw, shw) + xb.y, 0.f);
    half_store4(o, g_xf + (size_t)i * 4);
}

// ================= launch =================
extern "C" void kernel_launch(void* const* d_in, const int* in_sizes, int n_in,
                              void* d_out, int out_size) {
    const float* x    = (const float*)d_in[0];
    const int*   esrc = (const int*)d_in[1];
    const int*   edst = (const int*)d_in[2];
    const float* ew   = (const float*)d_in[3];
    const float* Wr0  = (const float*)d_in[4];
    // b_rel0 (d_in[5]) cancels exactly under BN
    const float* Wo0  = (const float*)d_in[6];
    const float* Wr1  = (const float*)d_in[7];
    // b_rel1 (d_in[8]) cancels under BN
    const float* Wo1  = (const float*)d_in[9];
    const float* Wr2  = (const float*)d_in[10];
    const float* b2   = (const float*)d_in[11];
    const float* Wo2  = (const float*)d_in[12];
    const float* gamma0 = (const float*)d_in[13];
    const float* beta0  = (const float*)d_in[14];
    const float* gamma1 = (const float*)d_in[15];
    const float* beta1  = (const float*)d_in[16];
    float* out = (float*)d_out;

    __half *aggf, *xf, *hf, *bt0, *bt1, *bt2;
    int* cnt;
    cudaGetSymbolAddress((void**)&cnt, g_cnt);
    cudaGetSymbolAddress((void**)&hf, g_hf);
    cudaGetSymbolAddress((void**)&aggf, g_aggf);
    cudaGetSymbolAddress((void**)&xf, g_xf);
    cudaGetSymbolAddress((void**)&bt0, g_bt0);
    cudaGetSymbolAddress((void**)&bt1, g_bt1);
    cudaGetSymbolAddress((void**)&bt2, g_bt2);

    const int SMEM128 = 2 * 128 * 144 + 2 * 128 * 144;  // 73728
    const int SMEM64  = 2 * 128 * 144 + 2 * 64 * 144;   // 55296
    cudaFuncSetAttribute((const void*)mma_gemm_kernel<128, 4, true, true>,
                         cudaFuncAttributeMaxDynamicSharedMemorySize, SMEM128);
    cudaFuncSetAttribute((const void*)mma_gemm_kernel<64, 4, false, false>,
                         cudaFuncAttributeMaxDynamicSharedMemorySize, SMEM64);

    const int EB = (N_EDGES + 255) / 256;
    const int AGG_B = (N_NODES + 7) / 8;
    const int GEMM_B = (N_NODES + 127) / 128;
    const int APPLY_B = (N_NODES * (C / 4) + 255) / 256;

    cudaMemsetAsync(cnt, 0, N_NODES * sizeof(int));
    build_kernel<<<EB, 256>>>(esrc, edst, ew);
    setup_kernel<<<APPLY_B, 256>>>(x, Wr0, Wo0, Wr1, Wo1, Wr2, Wo2);

    // ---- layer 0 ----
    aggregate_kernel<<<AGG_B, 256>>>();
    mma_gemm_kernel<128, 4, true, true><<<GEMM_B, 256, SMEM128>>>(
        aggf, xf, bt0, nullptr, hf, 0);
    bn_apply_kernel<<<APPLY_B, 256>>>(gamma0, beta0, 0);

    // ---- layer 1 ----
    aggregate_kernel<<<AGG_B, 256>>>();
    mma_gemm_kernel<128, 4, true, true><<<GEMM_B, 256, SMEM128>>>(
        aggf, xf, bt1, nullptr, hf, 1);
    bn_apply_kernel<<<APPLY_B, 256>>>(gamma1, beta1, 1);

    // ---- layer 2 ----
    aggregate_kernel<<<AGG_B, 256>>>();
    mma_gemm_kernel<64, 4, false, false><<<GEMM_B, 256, SMEM64>>>(
        aggf, xf, bt2, b2, out, 0);
}